// round 16
// baseline (speedup 1.0000x reference)
// AttentiveLinear as ONE symmetric-reduced GEMM [8192 x 8832] x [8832 x 128]:
//   y[n,o] = sum_{j<=i} x_j x_i Wfold[j,i,o] + sum_i x_i (Wb+bw)[i,o] + bb[o]
// R15: co-residency x2 via M-tile 16 (grid 512, all CTAs resident, ~14
// warps/SM). Cooperative A-build (64 threads) into SMEM fp16 frags; B via
// cp.async 3-stage ring in fragment order. fp16 m16n8k16, 4 warps x (16Mx32N).
#include <cuda_runtime.h>
#include <cuda_fp16.h>
#include <cstdint>
#include <cstddef>

static constexpr int NK = 8832;        // 8704 pair rows (j-grouped, even-based, 8-padded) + 128 bias
static constexpr int PAIRS = 8704;
static constexpr int NKB = 276;        // NK / 32
static constexpr int NCHUNK = 1104;    // NK / 8

// g_Wh: fp16 B operand in per-kb fragment order for m16n8k16 (as R12/R13):
//   u32 index = kb*2048 + ((ks2*4 + wn)*32 + gid*4+tg)*8 + nt*2 + reg
__device__ __align__(16) __half g_Wh[NK * 128];
__device__ uint32_t g_cidx[NCHUNK];    // (j<<16)|(i0<<8); j==255 -> bias rows; i0 even

__device__ __forceinline__ uint32_t smem_u32(const void* p) {
    uint32_t a;
    asm("{ .reg .u64 t; cvta.to.shared.u64 t, %1; cvt.u32.u64 %0, t; }" : "=r"(a) : "l"(p));
    return a;
}
__device__ __forceinline__ uint32_t packh2(float lo, float hi) {
    __half2 h = __floats2half2_rn(lo, hi);
    return *reinterpret_cast<uint32_t*>(&h);
}

// ---------------- prep kernel (unchanged from R13) ----------------
__global__ void k_prepW(const float* __restrict__ Ww, const float* __restrict__ Wb,
                        const float* __restrict__ bw) {
    __shared__ int sj, se;
    const int t = blockIdx.x, o = threadIdx.x;
    if (threadIdx.x == 0) {
        int j = 0, e = 0;
        if (t < PAIRS) {
            int s = 0;
            for (j = 0; j < 128; j++) {
                const int ib = j & ~1;
                const int len = ((128 - ib) + 7) & ~7;
                if (t < s + len) break;
                s += len;
            }
            e = t - s;
        } else {
            j = 255; e = t - PAIRS;     // bias rows, i = e
        }
        sj = j; se = e;
        if ((t & 7) == 0) {
            int i0 = (j == 255) ? e : ((j & ~1) + e);   // i0 even
            g_cidx[t >> 3] = ((uint32_t)j << 16) | ((uint32_t)i0 << 8);
        }
    }
    __syncthreads();
    const int j = sj, e = se;
    float v = 0.0f;
    if (j == 255) {
        v = Wb[e * 128 + o] + bw[e * 128 + o];
    } else {
        const int i = (j & ~1) + e;
        if (i == j)            v = Ww[(size_t)j * 16384 + j * 128 + o];
        else if (i > j && i < 128)
            v = Ww[(size_t)j * 16384 + i * 128 + o]
              + Ww[(size_t)i * 16384 + j * 128 + o];
        // i<j or i>=128: zero padding row
    }
    const int kb = t >> 5, kin = t & 31, ks2 = kin >> 4, kk = kin & 15;
    const int reg = kk >> 3, tg = (kk & 7) >> 1, hlf = kk & 1;
    const int wn = o >> 5, nn = o & 31, nt = nn >> 3, gid = nn & 7;
    const size_t u32idx = (size_t)kb * 2048 + ((ks2 * 4 + wn) * 32 + gid * 4 + tg) * 8 + nt * 2 + reg;
    g_Wh[u32idx * 2 + hlf] = __float2half_rn(v);
}

// ---------------- main kernel ----------------
// SMEM: X[16][132]f @0 (8448) | cidx u32[1104] @8448 (4416)
//       A frags u32 [2][256] @12864 (2048) | B fp16 [3][8KB] @14912 (24576)
static constexpr int X_OFF = 0;
static constexpr int CIDX_OFF = 8448;
static constexpr int A_OFF = 12864;
static constexpr int B_OFF = 14912;
static constexpr int SMEM_TOTAL = 39488;

__global__ void __launch_bounds__(128, 4) k_main(const float* __restrict__ x,
                                                 const float* __restrict__ bb,
                                                 float* __restrict__ y) {
    extern __shared__ char smem[];
    float*    sX = (float*)(smem + X_OFF);
    uint32_t* sC = (uint32_t*)(smem + CIDX_OFF);

    const int tid = threadIdx.x;
    const int m0 = blockIdx.x * 16;
    const int lane = tid & 31, wn = tid >> 5;    // 4 warps: each 16(M) x 32(N)
    const int gid = lane >> 2, tg = lane & 3;

    // Prologue: X tile (16 x 128, row stride 132) + chunk index table
    {
        const int r = tid >> 3, q = tid & 7;
        const float4* src = (const float4*)(x + (size_t)(m0 + r) * 128) + q * 4;
        float4* dst = (float4*)(sX + r * 132) + q * 4;
#pragma unroll
        for (int c = 0; c < 4; c++) dst[c] = src[c];
    }
#pragma unroll
    for (int k = 0; k < 9; k++) {
        int e = tid + k * 128;
        if (e < NCHUNK) sC[e] = g_cidx[e];
    }

    // B staging: 8KB per kb via cp.async (fragment-ordered source)
    auto cpasyncB = [&](int kb, int st) {
        const __half* srcbase = g_Wh + (size_t)kb * 4096;
        const uint32_t dstbase = smem_u32(smem + B_OFF + st * 8192);
#pragma unroll
        for (int c = 0; c < 4; c++) {
            const int chunk = tid + c * 128;          // 512 chunks of 16B
            asm volatile("cp.async.cg.shared.global [%0], [%1], 16;"
                         :: "r"(dstbase + (uint32_t)(chunk * 16)),
                            "l"(srcbase + chunk * 8));
        }
        asm volatile("cp.async.commit_group;");
    };

    // Cooperative A-frag builder: threads 0..63 each build one 4-reg fragment
    // for (ks2 = tid>>5, lane' = tid&31); one STS.128.
    auto buildA = [&](int kb, int st) {
        if (tid < 64) {
            const uint32_t* ce = sC + kb * 4;
            const int ks2 = tid >> 5, l = tid & 31;
            const int g = l >> 2, tgg = l & 3;
            const float* X0 = sX + g * 132;
            const float* X1 = X0 + 8 * 132;
            const uint32_t e0 = ce[ks2 * 2], e1 = ce[ks2 * 2 + 1];
            const int j0 = e0 >> 16, j1 = e1 >> 16;
            int p0 = (int)((e0 >> 8) & 255) + 2 * tgg; p0 = p0 < 126 ? p0 : 126;
            int p1 = (int)((e1 >> 8) & 255) + 2 * tgg; p1 = p1 < 126 ? p1 : 126;
            const float xj00 = (j0 == 255) ? 1.0f : X0[j0];
            const float xj01 = (j0 == 255) ? 1.0f : X1[j0];
            const float xj10 = (j1 == 255) ? 1.0f : X0[j1];
            const float xj11 = (j1 == 255) ? 1.0f : X1[j1];
            const float2 v00 = *(const float2*)(X0 + p0);   // p even -> aligned
            const float2 v01 = *(const float2*)(X1 + p0);
            const float2 v10 = *(const float2*)(X0 + p1);
            const float2 v11 = *(const float2*)(X1 + p1);
            uint4 w;
            w.x = packh2(xj00 * v00.x, xj00 * v00.y);
            w.y = packh2(xj01 * v01.x, xj01 * v01.y);
            w.z = packh2(xj10 * v10.x, xj10 * v10.y);
            w.w = packh2(xj11 * v11.x, xj11 * v11.y);
            ((uint4*)(smem + A_OFF + st * 1024))[tid] = w;
        }
    };
    __syncthreads();

    // Prologue: B(0), B(1) in flight; A(0) built
    cpasyncB(0, 0);
    cpasyncB(1, 1);
    buildA(0, 0);
    asm volatile("cp.async.wait_group 1;");       // B(0) resident
    __syncthreads();

    float acc[4][4] = {};
    int curB = 0, nxtB = 2;

    for (int kb = 0; kb < NKB; kb++) {
        const int curA = kb & 1;
        if (kb + 2 < NKB) cpasyncB(kb + 2, nxtB);
        else asm volatile("cp.async.commit_group;");    // uniform group count
        if (kb + 1 < NKB) buildA(kb + 1, curA ^ 1);     // overlaps with MMA below

        const uint4* Af = (const uint4*)(smem + A_OFF + curA * 1024);
        const char*  Bs = smem + B_OFF + curB * 8192;
#pragma unroll
        for (int ks2 = 0; ks2 < 2; ks2++) {
            // B fragments for all 4 nt tiles: 2 x LDS.128
            const uint4 q0 = *(const uint4*)(Bs + ((ks2 * 4 + wn) * 32 + lane) * 32);
            const uint4 q1 = *(const uint4*)(Bs + ((ks2 * 4 + wn) * 32 + lane) * 32 + 16);
            const uint32_t br[4][2] = {{q0.x, q0.y}, {q0.z, q0.w},
                                       {q1.x, q1.y}, {q1.z, q1.w}};
            const uint4 av = Af[ks2 * 32 + lane];
#pragma unroll
            for (int nt = 0; nt < 4; nt++) {
                asm volatile(
                    "mma.sync.aligned.m16n8k16.row.col.f32.f16.f16.f32 "
                    "{%0,%1,%2,%3}, {%4,%5,%6,%7}, {%8,%9}, {%0,%1,%2,%3};"
                    : "+f"(acc[nt][0]), "+f"(acc[nt][1]),
                      "+f"(acc[nt][2]), "+f"(acc[nt][3])
                    : "r"(av.x), "r"(av.y), "r"(av.z), "r"(av.w),
                      "r"(br[nt][0]), "r"(br[nt][1]));
            }
        }
        asm volatile("cp.async.wait_group 1;");   // B(kb+1) resident
        __syncthreads();
        curB = (curB == 2) ? 0 : curB + 1;
        nxtB = (nxtB == 2) ? 0 : nxtB + 1;
    }

    // Epilogue: add bb, store
    const int mrow = m0 + gid;
#pragma unroll
    for (int nt = 0; nt < 4; nt++) {
        const int n = wn * 32 + nt * 8 + tg * 2;
        const float c0 = __ldg(bb + n), c1 = __ldg(bb + n + 1);
        float* p0 = y + (size_t)mrow * 128 + n;
        float* p1 = p0 + 8 * 128;
        ((float2*)p0)[0] = make_float2(acc[nt][0] + c0, acc[nt][1] + c1);
        ((float2*)p1)[0] = make_float2(acc[nt][2] + c0, acc[nt][3] + c1);
    }
}

extern "C" void kernel_launch(void* const* d_in, const int* in_sizes, int n_in,
                              void* d_out, int out_size) {
    const float* x  = (const float*)d_in[0];
    const float* Wb = (const float*)d_in[1];
    const float* bb = (const float*)d_in[2];
    const float* Ww = (const float*)d_in[3];
    const float* bw = (const float*)d_in[4];
    float* y = (float*)d_out;

    static bool attr_set = false;
    if (!attr_set) {
        cudaFuncSetAttribute(k_main, cudaFuncAttributeMaxDynamicSharedMemorySize, SMEM_TOTAL);
        attr_set = true;
    }

    k_prepW<<<NK, 128>>>(Ww, Wb, bw);
    k_main<<<512, 128, SMEM_TOTAL>>>(x, bb, y);
}

// round 17
// speedup vs baseline: 1.4427x; 1.4427x over previous
// AttentiveLinear as ONE symmetric-reduced GEMM [8192 x 8832] x [8832 x 128]:
//   y[n,o] = sum_{j<=i} x_j x_i Wfold[j,i,o] + sum_i x_i (Wb+bw)[i,o] + bb[o]
// R16: R13 structure (M-tile 32, 4 warps x 32Mx32N, coop A-build, cp.async B)
// + K-SPLIT x2: grid 512 = 256 M-tiles x 2 K-halves -> ~14 warps/SM with
// per-SM pipe totals unchanged. Deterministic partials + tiny reduce kernel.
#include <cuda_runtime.h>
#include <cuda_fp16.h>
#include <cstdint>
#include <cstddef>

static constexpr int NK = 8832;        // 8704 pair rows (j-grouped, even-based, 8-padded) + 128 bias
static constexpr int PAIRS = 8704;
static constexpr int NKB = 276;        // NK / 32
static constexpr int HKB = 138;        // K-blocks per half
static constexpr int NCHUNK = 1104;    // NK / 8

// g_Wh: fp16 B operand in per-kb fragment order for m16n8k16 (as R12/R13):
//   u32 index = kb*2048 + ((ks2*4 + wn)*32 + gid*4+tg)*8 + nt*2 + reg
__device__ __align__(16) __half g_Wh[NK * 128];
__device__ uint32_t g_cidx[NCHUNK];    // (j<<16)|(i0<<8); j==255 -> bias rows; i0 even
__device__ __align__(16) float g_part[2 * 8192 * 128];   // K-split partials

__device__ __forceinline__ uint32_t smem_u32(const void* p) {
    uint32_t a;
    asm("{ .reg .u64 t; cvta.to.shared.u64 t, %1; cvt.u32.u64 %0, t; }" : "=r"(a) : "l"(p));
    return a;
}
__device__ __forceinline__ uint32_t packh2(float lo, float hi) {
    __half2 h = __floats2half2_rn(lo, hi);
    return *reinterpret_cast<uint32_t*>(&h);
}

// ---------------- prep kernel (unchanged from R13) ----------------
__global__ void k_prepW(const float* __restrict__ Ww, const float* __restrict__ Wb,
                        const float* __restrict__ bw) {
    __shared__ int sj, se;
    const int t = blockIdx.x, o = threadIdx.x;
    if (threadIdx.x == 0) {
        int j = 0, e = 0;
        if (t < PAIRS) {
            int s = 0;
            for (j = 0; j < 128; j++) {
                const int ib = j & ~1;
                const int len = ((128 - ib) + 7) & ~7;
                if (t < s + len) break;
                s += len;
            }
            e = t - s;
        } else {
            j = 255; e = t - PAIRS;     // bias rows, i = e
        }
        sj = j; se = e;
        if ((t & 7) == 0) {
            int i0 = (j == 255) ? e : ((j & ~1) + e);   // i0 even
            g_cidx[t >> 3] = ((uint32_t)j << 16) | ((uint32_t)i0 << 8);
        }
    }
    __syncthreads();
    const int j = sj, e = se;
    float v = 0.0f;
    if (j == 255) {
        v = Wb[e * 128 + o] + bw[e * 128 + o];
    } else {
        const int i = (j & ~1) + e;
        if (i == j)            v = Ww[(size_t)j * 16384 + j * 128 + o];
        else if (i > j && i < 128)
            v = Ww[(size_t)j * 16384 + i * 128 + o]
              + Ww[(size_t)i * 16384 + j * 128 + o];
        // i<j or i>=128: zero padding row
    }
    const int kb = t >> 5, kin = t & 31, ks2 = kin >> 4, kk = kin & 15;
    const int reg = kk >> 3, tg = (kk & 7) >> 1, hlf = kk & 1;
    const int wn = o >> 5, nn = o & 31, nt = nn >> 3, gid = nn & 7;
    const size_t u32idx = (size_t)kb * 2048 + ((ks2 * 4 + wn) * 32 + gid * 4 + tg) * 8 + nt * 2 + reg;
    g_Wh[u32idx * 2 + hlf] = __float2half_rn(v);
}

// ---------------- main kernel (one K-half per CTA) ----------------
// SMEM: X[32][132]f @0 (16896) | cidx u32[1104] @16896 (4416)
//       A frags u32 [2][512] @21312 (4096) | B fp16 [3][8KB] @25408 (24576)
static constexpr int X_OFF = 0;
static constexpr int CIDX_OFF = 16896;
static constexpr int A_OFF = 21312;
static constexpr int B_OFF = 25408;
static constexpr int SMEM_TOTAL = 49984;

__global__ void __launch_bounds__(128, 4) k_main(const float* __restrict__ x) {
    extern __shared__ char smem[];
    float*    sX = (float*)(smem + X_OFF);
    uint32_t* sC = (uint32_t*)(smem + CIDX_OFF);

    const int tid = threadIdx.x;
    const int tile = blockIdx.x >> 1;
    const int kh = blockIdx.x & 1;               // K-half
    const int m0 = tile * 32;
    const int KB0 = kh * HKB;
    const int lane = tid & 31, wn = tid >> 5;    // 4 warps: each 32(M) x 32(N)
    const int gid = lane >> 2, tg = lane & 3;

    // Prologue: X tile (32 x 128, row stride 132) + chunk index table
    {
        const int r = tid >> 2, q = tid & 3;
        const float4* src = (const float4*)(x + (size_t)(m0 + r) * 128) + q * 8;
        float4* dst = (float4*)(sX + r * 132) + q * 8;
#pragma unroll
        for (int c = 0; c < 8; c++) dst[c] = src[c];
    }
#pragma unroll
    for (int k = 0; k < 9; k++) {
        int e = tid + k * 128;
        if (e < NCHUNK) sC[e] = g_cidx[e];
    }

    // B staging: 8KB per kb via cp.async (fragment-ordered source)
    auto cpasyncB = [&](int kb, int st) {
        const __half* srcbase = g_Wh + (size_t)kb * 4096;
        const uint32_t dstbase = smem_u32(smem + B_OFF + st * 8192);
#pragma unroll
        for (int c = 0; c < 4; c++) {
            const int chunk = tid + c * 128;          // 512 chunks of 16B
            asm volatile("cp.async.cg.shared.global [%0], [%1], 16;"
                         :: "r"(dstbase + (uint32_t)(chunk * 16)),
                            "l"(srcbase + chunk * 8));
        }
        asm volatile("cp.async.commit_group;");
    };

    // Cooperative A-frag builder: thread tid builds the full 4-reg fragment
    // for (mt = tid>>6, ks2 = (tid>>5)&1, lane' = tid&31); one STS.128.
    auto buildA = [&](int kb, int st) {
        const uint32_t* ce = sC + kb * 4;
        const int mt = tid >> 6, ks2 = (tid >> 5) & 1, l = tid & 31;
        const int g = l >> 2, tgg = l & 3;
        const float* X0 = sX + (mt * 16 + g) * 132;
        const float* X1 = X0 + 8 * 132;
        const uint32_t e0 = ce[ks2 * 2], e1 = ce[ks2 * 2 + 1];
        const int j0 = e0 >> 16, j1 = e1 >> 16;
        int p0 = (int)((e0 >> 8) & 255) + 2 * tgg; p0 = p0 < 126 ? p0 : 126;
        int p1 = (int)((e1 >> 8) & 255) + 2 * tgg; p1 = p1 < 126 ? p1 : 126;
        const float xj00 = (j0 == 255) ? 1.0f : X0[j0];
        const float xj01 = (j0 == 255) ? 1.0f : X1[j0];
        const float xj10 = (j1 == 255) ? 1.0f : X0[j1];
        const float xj11 = (j1 == 255) ? 1.0f : X1[j1];
        const float2 v00 = *(const float2*)(X0 + p0);   // p even -> aligned
        const float2 v01 = *(const float2*)(X1 + p0);
        const float2 v10 = *(const float2*)(X0 + p1);
        const float2 v11 = *(const float2*)(X1 + p1);
        uint4 w;
        w.x = packh2(xj00 * v00.x, xj00 * v00.y);
        w.y = packh2(xj01 * v01.x, xj01 * v01.y);
        w.z = packh2(xj10 * v10.x, xj10 * v10.y);
        w.w = packh2(xj11 * v11.x, xj11 * v11.y);
        ((uint4*)(smem + A_OFF + st * 2048))[tid] = w;
    };
    __syncthreads();

    // Prologue: B(KB0), B(KB0+1) in flight; A(KB0) built
    cpasyncB(KB0, 0);
    cpasyncB(KB0 + 1, 1);
    buildA(KB0, 0);
    asm volatile("cp.async.wait_group 1;");       // B(KB0) resident
    __syncthreads();

    float acc[2][4][4] = {};
    int curB = 0, nxtB = 2;

    for (int lb = 0; lb < HKB; lb++) {
        const int kb = KB0 + lb;
        const int curA = lb & 1;
        if (lb + 2 < HKB) cpasyncB(kb + 2, nxtB);
        else asm volatile("cp.async.commit_group;");    // uniform group count
        if (lb + 1 < HKB) buildA(kb + 1, curA ^ 1);     // overlaps with MMA below

        const uint4* Af = (const uint4*)(smem + A_OFF + curA * 2048);
        const char*  Bs = smem + B_OFF + curB * 8192;
#pragma unroll
        for (int ks2 = 0; ks2 < 2; ks2++) {
            // B fragments for all 4 nt tiles: 2 x LDS.128
            const uint4 q0 = *(const uint4*)(Bs + ((ks2 * 4 + wn) * 32 + lane) * 32);
            const uint4 q1 = *(const uint4*)(Bs + ((ks2 * 4 + wn) * 32 + lane) * 32 + 16);
            const uint32_t br[4][2] = {{q0.x, q0.y}, {q0.z, q0.w},
                                       {q1.x, q1.y}, {q1.z, q1.w}};
#pragma unroll
            for (int mt = 0; mt < 2; mt++) {
                const uint4 av = Af[(mt * 2 + ks2) * 32 + lane];
#pragma unroll
                for (int nt = 0; nt < 4; nt++) {
                    asm volatile(
                        "mma.sync.aligned.m16n8k16.row.col.f32.f16.f16.f32 "
                        "{%0,%1,%2,%3}, {%4,%5,%6,%7}, {%8,%9}, {%0,%1,%2,%3};"
                        : "+f"(acc[mt][nt][0]), "+f"(acc[mt][nt][1]),
                          "+f"(acc[mt][nt][2]), "+f"(acc[mt][nt][3])
                        : "r"(av.x), "r"(av.y), "r"(av.z), "r"(av.w),
                          "r"(br[nt][0]), "r"(br[nt][1]));
                }
            }
        }
        asm volatile("cp.async.wait_group 1;");   // B(kb+1) resident
        __syncthreads();
        curB = (curB == 2) ? 0 : curB + 1;
        nxtB = (nxtB == 2) ? 0 : nxtB + 1;
    }

    // Epilogue: store partials (no bb here; reduce kernel adds it)
    float* part = g_part + (size_t)kh * (8192 * 128);
#pragma unroll
    for (int mt = 0; mt < 2; mt++) {
        const int mrow = m0 + mt * 16 + gid;
#pragma unroll
        for (int nt = 0; nt < 4; nt++) {
            const int n = wn * 32 + nt * 8 + tg * 2;
            float* p0 = part + (size_t)mrow * 128 + n;
            float* p1 = p0 + 8 * 128;
            ((float2*)p0)[0] = make_float2(acc[mt][nt][0], acc[mt][nt][1]);
            ((float2*)p1)[0] = make_float2(acc[mt][nt][2], acc[mt][nt][3]);
        }
    }
}

// ---------------- reduce: y = part0 + part1 + bb ----------------
__global__ void k_reduce(const float* __restrict__ bb, float* __restrict__ y) {
    const int idx = (blockIdx.x * 256 + threadIdx.x) * 4;   // 1M floats total
    const float4 a = *(const float4*)(g_part + idx);
    const float4 b = *(const float4*)(g_part + 8192 * 128 + idx);
    const float4 c = *(const float4*)(bb + (idx & 127));
    float4 r;
    r.x = a.x + b.x + c.x;
    r.y = a.y + b.y + c.y;
    r.z = a.z + b.z + c.z;
    r.w = a.w + b.w + c.w;
    *(float4*)(y + idx) = r;
}

extern "C" void kernel_launch(void* const* d_in, const int* in_sizes, int n_in,
                              void* d_out, int out_size) {
    const float* x  = (const float*)d_in[0];
    const float* Wb = (const float*)d_in[1];
    const float* bb = (const float*)d_in[2];
    const float* Ww = (const float*)d_in[3];
    const float* bw = (const float*)d_in[4];
    float* y = (float*)d_out;

    static bool attr_set = false;
    if (!attr_set) {
        cudaFuncSetAttribute(k_main, cudaFuncAttributeMaxDynamicSharedMemorySize, SMEM_TOTAL);
        attr_set = true;
    }

    k_prepW<<<NK, 128>>>(Ww, Wb, bw);
    k_main<<<512, 128, SMEM_TOTAL>>>(x);
    k_reduce<<<1024, 256>>>(bb, y);
}